// round 10
// baseline (speedup 1.0000x reference)
#include <cuda_runtime.h>

// x: (B=16, C=256, L=16384) fp32, kernel=4, stride=4 -> out (B, 256, 4096) fp32
// c_curv = 1.0, eps = 1e-7
#define C_CH    256
#define L_IN    16384
#define OUT_LEN 4096
#define EPS_F   1e-7f

// Block: 256 threads = 8 warps, 8 output columns x 256 channels.
// Thread t: column j = t&7, channel group cg = t>>3 (0..31), channels cg+32i.
//   Reads:  per-warp 128B contiguous runs per channel row (8 x LDG.128/thread).
//   Writes: one full 32B sector per channel row per warp instruction; the 4
//           sibling blocks' sectors merge into full 128B lines in L2.
// Reduction: 4x4 window Gram matrix (10 sums, padded to 12 for float4 smem).
//   in-warp shfl_xor(8,16) -> lanes 0..7 hold per-warp partials (col = lane),
//   stored as 3 x STS.128. One barrier, then threads 0..7 (one per column)
//   do the cross-warp sum with LDS.128 + scalar math. Second barrier, fused
//   epilogue. 2 barriers total. (256,5) caps regs at 48 -> ~62% occupancy.
__global__ __launch_bounds__(256, 5) void hpool_kernel(
    const float* __restrict__ x, float* __restrict__ out)
{
    __shared__ float4 red[8 * 8 * 3];   // [warp][col][3] — 12 padded floats
    __shared__ float  cf[8][4];         // [col][p] fused coefficients

    const int t    = threadIdx.x;
    const int j    = t & 7;
    const int cg   = t >> 3;       // 0..31
    const int lane = t & 31;
    const int warp = t >> 5;
    const int l0   = blockIdx.x * 8;
    const int b    = blockIdx.y;

    // ---- load window: 8 channels x 4 positions, one float4 each ----
    const unsigned base_in = (unsigned)b * (C_CH * L_IN) + (unsigned)(l0 + j) * 4;
    float4 w[8];
#pragma unroll
    for (int i = 0; i < 8; i++) {
        w[i] = *reinterpret_cast<const float4*>(
            x + base_in + (unsigned)(cg + 32 * i) * L_IN);
    }

    // ---- Gram partials: s0..3 diag; s4..9 = (0,1)(0,2)(0,3)(1,2)(1,3)(2,3) ----
    float s[10];
#pragma unroll
    for (int q = 0; q < 10; q++) s[q] = 0.f;
#pragma unroll
    for (int i = 0; i < 8; i++) {
        const float a0 = w[i].x, a1 = w[i].y, a2 = w[i].z, a3 = w[i].w;
        s[0] += a0 * a0; s[1] += a1 * a1; s[2] += a2 * a2; s[3] += a3 * a3;
        s[4] += a0 * a1; s[5] += a0 * a2; s[6] += a0 * a3;
        s[7] += a1 * a2; s[8] += a1 * a3; s[9] += a2 * a3;
    }
    // reduce across the 4 channel-group lanes sharing column j
#pragma unroll
    for (int q = 0; q < 10; q++) {
        s[q] += __shfl_xor_sync(0xffffffffu, s[q], 8);
        s[q] += __shfl_xor_sync(0xffffffffu, s[q], 16);
    }

    // lanes 0..7 store 12 padded floats as 3 x STS.128
    // bank base = (lane*12) mod 32 = {0,12,24,4,16,28,8,20} -> conflict-free
    if (lane < 8) {
        const int rbase = (warp * 8 + lane) * 3;
        red[rbase + 0] = make_float4(s[0], s[1], s[2], s[3]);
        red[rbase + 1] = make_float4(s[4], s[5], s[6], s[7]);
        red[rbase + 2] = make_float4(s[8], s[9], 0.f, 0.f);
    }
    __syncthreads();

    // ---- fused cross-warp sum + scalar math: threads 0..7 (one per column) ----
    if (t < 8) {
        float4 g0 = red[t * 3 + 0], g1 = red[t * 3 + 1], g2 = red[t * 3 + 2];
#pragma unroll
        for (int wq = 1; wq < 8; wq++) {
            const int rbase = (wq * 8 + t) * 3;
            const float4 r0 = red[rbase + 0];
            const float4 r1 = red[rbase + 1];
            const float4 r2 = red[rbase + 2];
            g0.x += r0.x; g0.y += r0.y; g0.z += r0.z; g0.w += r0.w;
            g1.x += r1.x; g1.y += r1.y; g1.z += r1.z; g1.w += r1.w;
            g2.x += r2.x; g2.y += r2.y;
        }
        // diag = g0.{x,y,z,w}; off: g1 = G01,G02,G03,G12; g2.{x,y} = G13,G23
        const float f0 = 2.0f / (1.0f + g0.x);
        const float f1 = 2.0f / (1.0f + g0.y);
        const float f2 = 2.0f / (1.0f + g0.z);
        const float f3 = 2.0f / (1.0f + g0.w);
        const float ga0 = rsqrtf(fmaxf(1.0f - f0 * f0 * g0.x, EPS_F));
        const float ga1 = rsqrtf(fmaxf(1.0f - f1 * f1 * g0.y, EPS_F));
        const float ga2 = rsqrtf(fmaxf(1.0f - f2 * f2 * g0.z, EPS_F));
        const float ga3 = rsqrtf(fmaxf(1.0f - f3 * f3 * g0.w, EPS_F));
        const float inv_d = 1.0f / (ga0 + ga1 + ga2 + ga3);
        const float c0 = ga0 * f0 * inv_d;
        const float c1 = ga1 * f1 * inv_d;
        const float c2 = ga2 * f2 * inv_d;
        const float c3 = ga3 * f3 * inv_d;

        const float mk2 =
            c0 * c0 * g0.x + c1 * c1 * g0.y + c2 * c2 * g0.z + c3 * c3 * g0.w +
            2.0f * (c0 * c1 * g1.x + c0 * c2 * g1.y + c0 * c3 * g1.z +
                    c1 * c2 * g1.w + c1 * c3 * g2.x + c2 * c3 * g2.y);

        const float sc = 1.0f / (1.0f + sqrtf(fmaxf(1.0f - mk2, EPS_F)));
        cf[t][0] = c0 * sc;
        cf[t][1] = c1 * sc;
        cf[t][2] = c2 * sc;
        cf[t][3] = c3 * sc;
    }
    __syncthreads();

    // ---- fused epilogue: out = sum_p cf[j][p] * w[:,p] ----
    const float c0 = cf[j][0], c1 = cf[j][1], c2 = cf[j][2], c3 = cf[j][3];
    const unsigned base_out = (unsigned)b * (C_CH * OUT_LEN) + (unsigned)(l0 + j);
#pragma unroll
    for (int i = 0; i < 8; i++) {
        out[base_out + (unsigned)(cg + 32 * i) * OUT_LEN] =
            c0 * w[i].x + c1 * w[i].y + c2 * w[i].z + c3 * w[i].w;
    }
}

extern "C" void kernel_launch(void* const* d_in, const int* in_sizes, int n_in,
                              void* d_out, int out_size)
{
    const float* x = (const float*)d_in[0];
    float* out = (float*)d_out;

    const int B = in_sizes[0] / (C_CH * L_IN);   // 16
    dim3 grid(OUT_LEN / 8, B);                   // (512, 16)
    hpool_kernel<<<grid, 256>>>(x, out);
}